// round 9
// baseline (speedup 1.0000x reference)
#include <cuda_runtime.h>
#include <cuda_fp16.h>
#include <cstdint>

typedef unsigned long long ull;

// ---------------------------------------------------------------------------
// Device scratch: featuremap as fp16, x-pair duplicated. Entry (y,x) is 16B:
//   [ c0..c3 @(y,x) , c0..c3 @(y,min(x+1,511)) ]  as 8 halves.
// One LDG.128 fetches BOTH x-taps of one row -> 2 loads per bilinear sample.
// ---------------------------------------------------------------------------
__device__ uint4 g_fmH[512 * 512];

__global__ void fm_pack_kernel(const float* __restrict__ fm) {
    int i = blockIdx.x * blockDim.x + threadIdx.x;
    if (i >= 512 * 512) return;
    int x  = i & 511;
    int xn = min(x + 1, 511);
    int j  = i - x + xn;

    __half2 p01 = __floats2half2_rn(fm[i],              fm[i + 262144]);
    __half2 p23 = __floats2half2_rn(fm[i + 2 * 262144], fm[i + 3 * 262144]);
    __half2 q01 = __floats2half2_rn(fm[j],              fm[j + 262144]);
    __half2 q23 = __floats2half2_rn(fm[j + 2 * 262144], fm[j + 3 * 262144]);

    uint4 e;
    e.x = *reinterpret_cast<unsigned*>(&p01);
    e.y = *reinterpret_cast<unsigned*>(&p23);
    e.z = *reinterpret_cast<unsigned*>(&q01);
    e.w = *reinterpret_cast<unsigned*>(&q23);
    g_fmH[i] = e;
}

// ---------------------------------------------------------------------------
// f32x2 packed helpers
// ---------------------------------------------------------------------------
__device__ __forceinline__ ull pack2(float lo, float hi) {
    ull r;
    asm("mov.b64 %0, {%1, %2};" : "=l"(r) : "f"(lo), "f"(hi));
    return r;
}
__device__ __forceinline__ void unpack2(ull v, float& lo, float& hi) {
    asm("mov.b64 {%0, %1}, %2;" : "=f"(lo), "=f"(hi) : "l"(v));
}
__device__ __forceinline__ ull ffma2(ull a, ull b, ull c) {
    ull d;
    asm("fma.rn.f32x2 %0, %1, %2, %3;" : "=l"(d) : "l"(a), "l"(b), "l"(c));
    return d;
}
// half2 (two points' activation) -> f32x2 pair
__device__ __forceinline__ ull h2_to_pair(__half2 h) {
    float2 f = __half22float2(h);
    return pack2(f.x, f.y);
}
// f32x2 acc -> relu -> half2
__device__ __forceinline__ __half2 pair_relu_h2(ull v) {
    float lo, hi;
    unpack2(v, lo, hi);
    return __floats2half2_rn(fmaxf(lo, 0.0f), fmaxf(hi, 0.0f));
}

// ---------------------------------------------------------------------------
// Bilinear sample, border clamp (identical math to reference).
// ---------------------------------------------------------------------------
__device__ __forceinline__ void sample_fm(float u, float v, float f[4]) {
    float fx = fminf(fmaxf(fmaf(u, 512.0f, -0.5f), 0.0f), 511.0f);
    float fy = fminf(fmaxf(fmaf(v, 512.0f, -0.5f), 0.0f), 511.0f);
    float x0f = floorf(fx), y0f = floorf(fy);
    float wx = fx - x0f, wy = fy - y0f;
    int ix0 = (int)x0f, iy0 = (int)y0f;
    int iy1 = min(iy0 + 1, 511);

    const uint4* fmH = g_fmH;
    uint4 r0 = __ldg(&fmH[iy0 * 512 + ix0]);
    uint4 r1 = __ldg(&fmH[iy1 * 512 + ix0]);

    float2 a01 = __half22float2(*reinterpret_cast<__half2*>(&r0.x));
    float2 a23 = __half22float2(*reinterpret_cast<__half2*>(&r0.y));
    float2 b01 = __half22float2(*reinterpret_cast<__half2*>(&r0.z));
    float2 b23 = __half22float2(*reinterpret_cast<__half2*>(&r0.w));
    float2 c01 = __half22float2(*reinterpret_cast<__half2*>(&r1.x));
    float2 c23 = __half22float2(*reinterpret_cast<__half2*>(&r1.y));
    float2 d01 = __half22float2(*reinterpret_cast<__half2*>(&r1.z));
    float2 d23 = __half22float2(*reinterpret_cast<__half2*>(&r1.w));

    float t0, t1;
    t0 = fmaf(wx, b01.x - a01.x, a01.x);
    t1 = fmaf(wx, d01.x - c01.x, c01.x);
    f[0] = fmaf(wy, t1 - t0, t0);
    t0 = fmaf(wx, b01.y - a01.y, a01.y);
    t1 = fmaf(wx, d01.y - c01.y, c01.y);
    f[1] = fmaf(wy, t1 - t0, t0);
    t0 = fmaf(wx, b23.x - a23.x, a23.x);
    t1 = fmaf(wx, d23.x - c23.x, c23.x);
    f[2] = fmaf(wy, t1 - t0, t0);
    t0 = fmaf(wx, b23.y - a23.y, a23.y);
    t1 = fmaf(wx, d23.y - c23.y, c23.y);
    f[3] = fmaf(wy, t1 - t0, t0);
}

// ---------------------------------------------------------------------------
// Hidden layer, k-outer, 32 independent f32x2 acc chains.
// in0/in1: 16 half2 activations (point-pair 0 / point-pair 1).
// out0/out1: 16 half2 relu'd outputs.
// ---------------------------------------------------------------------------
__device__ __forceinline__ void layer_h16(const ull* __restrict__ sW,
                                          const ull* __restrict__ sB,
                                          const __half2 in0[16],
                                          const __half2 in1[16],
                                          __half2 out0[16],
                                          __half2 out1[16]) {
    ull a[8], c[8], A[8], C[8];
#pragma unroll
    for (int jp = 0; jp < 8; jp++) {
        ull b0 = sB[2 * jp], b1 = sB[2 * jp + 1];
        a[jp] = b0; c[jp] = b1;
        A[jp] = b0; C[jp] = b1;
    }
#pragma unroll
    for (int k = 0; k < 16; k++) {
        ull a0 = h2_to_pair(in0[k]);
        ull a1 = h2_to_pair(in1[k]);
#pragma unroll
        for (int jp = 0; jp < 8; jp++) {
            ulonglong2 w = *reinterpret_cast<const ulonglong2*>(&sW[k * 16 + 2 * jp]);
            a[jp] = ffma2(a0, w.x, a[jp]);
            c[jp] = ffma2(a0, w.y, c[jp]);
            A[jp] = ffma2(a1, w.x, A[jp]);
            C[jp] = ffma2(a1, w.y, C[jp]);
        }
    }
#pragma unroll
    for (int jp = 0; jp < 8; jp++) {
        out0[2 * jp]     = pair_relu_h2(a[jp]);
        out0[2 * jp + 1] = pair_relu_h2(c[jp]);
        out1[2 * jp]     = pair_relu_h2(A[jp]);
        out1[2 * jp + 1] = pair_relu_h2(C[jp]);
    }
}

// First layer: 7 f32x2 inputs (coords + feat), 16 half2 outputs.
__device__ __forceinline__ void layer_first(const ull* __restrict__ sW,
                                            const ull* __restrict__ sB,
                                            const ull in0[7], const ull in1[7],
                                            __half2 out0[16], __half2 out1[16]) {
    ull a[8], c[8], A[8], C[8];
#pragma unroll
    for (int jp = 0; jp < 8; jp++) {
        ull b0 = sB[2 * jp], b1 = sB[2 * jp + 1];
        a[jp] = b0; c[jp] = b1;
        A[jp] = b0; C[jp] = b1;
    }
#pragma unroll
    for (int k = 0; k < 7; k++) {
        ull a0 = in0[k], a1 = in1[k];
#pragma unroll
        for (int jp = 0; jp < 8; jp++) {
            ulonglong2 w = *reinterpret_cast<const ulonglong2*>(&sW[k * 16 + 2 * jp]);
            a[jp] = ffma2(a0, w.x, a[jp]);
            c[jp] = ffma2(a0, w.y, c[jp]);
            A[jp] = ffma2(a1, w.x, A[jp]);
            C[jp] = ffma2(a1, w.y, C[jp]);
        }
    }
#pragma unroll
    for (int jp = 0; jp < 8; jp++) {
        out0[2 * jp]     = pair_relu_h2(a[jp]);
        out0[2 * jp + 1] = pair_relu_h2(c[jp]);
        out1[2 * jp]     = pair_relu_h2(A[jp]);
        out1[2 * jp + 1] = pair_relu_h2(C[jp]);
    }
}

// Final layer: 16 half2 in, 3 f32x2 out per pair-set (no relu).
__device__ __forceinline__ void layer_out_h(const ull* __restrict__ sW,
                                            const ull* __restrict__ sB,
                                            const __half2 in0[16],
                                            const __half2 in1[16],
                                            ull o0[3], ull o1[3]) {
#pragma unroll
    for (int j = 0; j < 3; j++) { o0[j] = sB[j]; o1[j] = sB[j]; }
#pragma unroll
    for (int k = 0; k < 16; k++) {
        ull a0 = h2_to_pair(in0[k]);
        ull a1 = h2_to_pair(in1[k]);
#pragma unroll
        for (int j = 0; j < 3; j++) {
            ull w = sW[k * 3 + j];
            o0[j] = ffma2(a0, w, o0[j]);
            o1[j] = ffma2(a1, w, o1[j]);
        }
    }
}

// ---------------------------------------------------------------------------
// Main fused kernel: 4 points per thread (2 f32x2 pair-sets).
// ---------------------------------------------------------------------------
__global__ __launch_bounds__(128, 4) void mlp_kernel(
    const float* __restrict__ x,
    const float* __restrict__ W1, const float* __restrict__ b1,
    const float* __restrict__ W2, const float* __restrict__ b2,
    const float* __restrict__ W3, const float* __restrict__ b3,
    const float* __restrict__ W4, const float* __restrict__ b4,
    const float* __restrict__ W5, const float* __restrict__ b5,
    float* __restrict__ out, int n)
{
    __shared__ alignas(16) ull sW1[7 * 16];
    __shared__ alignas(16) ull sW2[16 * 16];
    __shared__ alignas(16) ull sW3[16 * 16];
    __shared__ alignas(16) ull sW4[16 * 16];
    __shared__ alignas(16) ull sW5[16 * 3];
    __shared__ alignas(16) ull sB1[16], sB2[16], sB3[16], sB4[16], sB5[4];

    int tid = threadIdx.x;
    for (int i = tid; i < 112; i += 128) sW1[i] = pack2(W1[i], W1[i]);
    for (int i = tid; i < 256; i += 128) {
        sW2[i] = pack2(W2[i], W2[i]);
        sW3[i] = pack2(W3[i], W3[i]);
        sW4[i] = pack2(W4[i], W4[i]);
    }
    for (int i = tid; i < 48; i += 128) sW5[i] = pack2(W5[i], W5[i]);
    if (tid < 16) {
        sB1[tid] = pack2(b1[tid], b1[tid]);
        sB2[tid] = pack2(b2[tid], b2[tid]);
        sB3[tid] = pack2(b3[tid], b3[tid]);
        sB4[tid] = pack2(b4[tid], b4[tid]);
    }
    if (tid < 3) sB5[tid] = pack2(b5[tid], b5[tid]);
    __syncthreads();

    long base = (long)(blockIdx.x * 128 + tid) * 4;
    if (base >= n) return;

    // ---- load 4 points' coordinates ----
    float px[4], py[4], pz[4];
    if (base + 4 <= (long)n) {
        const float4* xv = reinterpret_cast<const float4*>(x + base * 3);
        float4 A = __ldg(xv), B = __ldg(xv + 1), C = __ldg(xv + 2);
        px[0] = A.x; py[0] = A.y; pz[0] = A.z;
        px[1] = A.w; py[1] = B.x; pz[1] = B.y;
        px[2] = B.z; py[2] = B.w; pz[2] = C.x;
        px[3] = C.y; py[3] = C.z; pz[3] = C.w;
    } else {
        float tmp[12];
        int cnt = (int)(n - base) * 3;
#pragma unroll
        for (int i = 0; i < 12; i++) tmp[i] = (i < cnt) ? x[base * 3 + i] : 0.0f;
#pragma unroll
        for (int p = 0; p < 4; p++) {
            px[p] = tmp[p * 3 + 0];
            py[p] = tmp[p * 3 + 1];
            pz[p] = tmp[p * 3 + 2];
        }
    }

    // ---- bilinear gather (2 x LDG.128 per point) ----
    float ft[4][4];
#pragma unroll
    for (int p = 0; p < 4; p++) sample_fm(px[p], py[p], ft[p]);

    // ---- first-layer inputs as f32x2 pairs ----
    ull u0[7], u1[7];
    u0[0] = pack2(px[0], px[1]);  u1[0] = pack2(px[2], px[3]);
    u0[1] = pack2(py[0], py[1]);  u1[1] = pack2(py[2], py[3]);
    u0[2] = pack2(pz[0], pz[1]);  u1[2] = pack2(pz[2], pz[3]);
#pragma unroll
    for (int c = 0; c < 4; c++) {
        u0[3 + c] = pack2(ft[0][c], ft[1][c]);
        u1[3 + c] = pack2(ft[2][c], ft[3][c]);
    }

    // ---- MLP (activations stored as half2 between layers) ----
    __half2 hA0[16], hA1[16], hB0[16], hB1[16];
    layer_first(sW1, sB1, u0, u1, hA0, hA1);
    layer_h16(sW2, sB2, hA0, hA1, hB0, hB1);
    layer_h16(sW3, sB3, hB0, hB1, hA0, hA1);
    layer_h16(sW4, sB4, hA0, hA1, hB0, hB1);

    ull o0[3], o1[3];
    layer_out_h(sW5, sB5, hB0, hB1, o0, o1);

    // ---- unpack + store 12 floats ----
    float r[12];
    unpack2(o0[0], r[0], r[3]);
    unpack2(o0[1], r[1], r[4]);
    unpack2(o0[2], r[2], r[5]);
    unpack2(o1[0], r[6], r[9]);
    unpack2(o1[1], r[7], r[10]);
    unpack2(o1[2], r[8], r[11]);

    if (base + 4 <= (long)n) {
        float4* ov = reinterpret_cast<float4*>(out + base * 3);
        ov[0] = make_float4(r[0], r[1], r[2], r[3]);
        ov[1] = make_float4(r[4], r[5], r[6], r[7]);
        ov[2] = make_float4(r[8], r[9], r[10], r[11]);
    } else {
        int cnt = (int)(n - base) * 3;
        for (int i = 0; i < cnt; i++) out[base * 3 + i] = r[i];
    }
}

// ---------------------------------------------------------------------------
// kernel_launch — graph-capturable, allocation-free.
// ---------------------------------------------------------------------------
extern "C" void kernel_launch(void* const* d_in, const int* in_sizes, int n_in,
                              void* d_out, int out_size) {
    const float* x  = (const float*)d_in[0];
    const float* fm = (const float*)d_in[1];
    const float* W1 = (const float*)d_in[2];
    const float* b1 = (const float*)d_in[3];
    const float* W2 = (const float*)d_in[4];
    const float* b2 = (const float*)d_in[5];
    const float* W3 = (const float*)d_in[6];
    const float* b3 = (const float*)d_in[7];
    const float* W4 = (const float*)d_in[8];
    const float* b4 = (const float*)d_in[9];
    const float* W5 = (const float*)d_in[10];
    const float* b5 = (const float*)d_in[11];

    int n = in_sizes[0] / 3;   // 4,000,000 points

    fm_pack_kernel<<<(512 * 512 + 255) / 256, 256>>>(fm);

    int nthreads = (n + 3) / 4;
    int nblocks  = (nthreads + 127) / 128;
    mlp_kernel<<<nblocks, 128>>>(x, W1, b1, W2, b2, W3, b3, W4, b4, W5, b5,
                                 (float*)d_out, n);
}

// round 10
// speedup vs baseline: 1.0580x; 1.0580x over previous
#include <cuda_runtime.h>
#include <cuda_fp16.h>
#include <cstdint>

typedef unsigned long long ull;

// ---------------------------------------------------------------------------
// Device scratch: featuremap as fp16, x-pair duplicated. Entry (y,x) is 16B:
//   [ c0..c3 @(y,x) , c0..c3 @(y,min(x+1,511)) ]  as 8 halves.
// One LDG.128 fetches BOTH x-taps of one row -> 2 loads per bilinear sample.
// ---------------------------------------------------------------------------
__device__ uint4 g_fmH[512 * 512];

__global__ void fm_pack_kernel(const float* __restrict__ fm) {
    int i = blockIdx.x * blockDim.x + threadIdx.x;
    if (i >= 512 * 512) return;
    int x  = i & 511;
    int xn = min(x + 1, 511);
    int j  = i - x + xn;

    __half2 p01 = __floats2half2_rn(fm[i],              fm[i + 262144]);
    __half2 p23 = __floats2half2_rn(fm[i + 2 * 262144], fm[i + 3 * 262144]);
    __half2 q01 = __floats2half2_rn(fm[j],              fm[j + 262144]);
    __half2 q23 = __floats2half2_rn(fm[j + 2 * 262144], fm[j + 3 * 262144]);

    uint4 e;
    e.x = *reinterpret_cast<unsigned*>(&p01);
    e.y = *reinterpret_cast<unsigned*>(&p23);
    e.z = *reinterpret_cast<unsigned*>(&q01);
    e.w = *reinterpret_cast<unsigned*>(&q23);
    g_fmH[i] = e;
}

// ---------------------------------------------------------------------------
// f32x2 packed helpers
// ---------------------------------------------------------------------------
__device__ __forceinline__ ull pack2(float lo, float hi) {
    ull r;
    asm("mov.b64 %0, {%1, %2};" : "=l"(r) : "f"(lo), "f"(hi));
    return r;
}
__device__ __forceinline__ void unpack2(ull v, float& lo, float& hi) {
    asm("mov.b64 {%0, %1}, %2;" : "=f"(lo), "=f"(hi) : "l"(v));
}
__device__ __forceinline__ ull ffma2(ull a, ull b, ull c) {
    ull d;
    asm("fma.rn.f32x2 %0, %1, %2, %3;" : "=l"(d) : "l"(a), "l"(b), "l"(c));
    return d;
}
// half2 (two points' activation) -> f32x2 pair
__device__ __forceinline__ ull h2_to_pair(__half2 h) {
    float2 f = __half22float2(h);
    return pack2(f.x, f.y);
}
// f32x2 acc -> relu -> half2
__device__ __forceinline__ __half2 pair_relu_h2(ull v) {
    float lo, hi;
    unpack2(v, lo, hi);
    return __floats2half2_rn(fmaxf(lo, 0.0f), fmaxf(hi, 0.0f));
}

// ---------------------------------------------------------------------------
// Bilinear sample, border clamp (identical math to reference).
// ---------------------------------------------------------------------------
__device__ __forceinline__ void sample_fm(float u, float v, float f[4]) {
    float fx = fminf(fmaxf(fmaf(u, 512.0f, -0.5f), 0.0f), 511.0f);
    float fy = fminf(fmaxf(fmaf(v, 512.0f, -0.5f), 0.0f), 511.0f);
    float x0f = floorf(fx), y0f = floorf(fy);
    float wx = fx - x0f, wy = fy - y0f;
    int ix0 = (int)x0f, iy0 = (int)y0f;
    int iy1 = min(iy0 + 1, 511);

    const uint4* fmH = g_fmH;
    uint4 r0 = __ldg(&fmH[iy0 * 512 + ix0]);
    uint4 r1 = __ldg(&fmH[iy1 * 512 + ix0]);

    float2 a01 = __half22float2(*reinterpret_cast<__half2*>(&r0.x));
    float2 a23 = __half22float2(*reinterpret_cast<__half2*>(&r0.y));
    float2 b01 = __half22float2(*reinterpret_cast<__half2*>(&r0.z));
    float2 b23 = __half22float2(*reinterpret_cast<__half2*>(&r0.w));
    float2 c01 = __half22float2(*reinterpret_cast<__half2*>(&r1.x));
    float2 c23 = __half22float2(*reinterpret_cast<__half2*>(&r1.y));
    float2 d01 = __half22float2(*reinterpret_cast<__half2*>(&r1.z));
    float2 d23 = __half22float2(*reinterpret_cast<__half2*>(&r1.w));

    float t0, t1;
    t0 = fmaf(wx, b01.x - a01.x, a01.x);
    t1 = fmaf(wx, d01.x - c01.x, c01.x);
    f[0] = fmaf(wy, t1 - t0, t0);
    t0 = fmaf(wx, b01.y - a01.y, a01.y);
    t1 = fmaf(wx, d01.y - c01.y, c01.y);
    f[1] = fmaf(wy, t1 - t0, t0);
    t0 = fmaf(wx, b23.x - a23.x, a23.x);
    t1 = fmaf(wx, d23.x - c23.x, c23.x);
    f[2] = fmaf(wy, t1 - t0, t0);
    t0 = fmaf(wx, b23.y - a23.y, a23.y);
    t1 = fmaf(wx, d23.y - c23.y, c23.y);
    f[3] = fmaf(wy, t1 - t0, t0);
}

// ---------------------------------------------------------------------------
// Hidden layer, k-outer, 32 independent f32x2 acc chains.
// in0/in1: 16 half2 activations (point-pair 0 / point-pair 1).
// out0/out1: 16 half2 relu'd outputs.
// ---------------------------------------------------------------------------
__device__ __forceinline__ void layer_h16(const ull* __restrict__ sW,
                                          const ull* __restrict__ sB,
                                          const __half2 in0[16],
                                          const __half2 in1[16],
                                          __half2 out0[16],
                                          __half2 out1[16]) {
    ull a[8], c[8], A[8], C[8];
#pragma unroll
    for (int jp = 0; jp < 8; jp++) {
        ull b0 = sB[2 * jp], b1 = sB[2 * jp + 1];
        a[jp] = b0; c[jp] = b1;
        A[jp] = b0; C[jp] = b1;
    }
#pragma unroll
    for (int k = 0; k < 16; k++) {
        ull a0 = h2_to_pair(in0[k]);
        ull a1 = h2_to_pair(in1[k]);
#pragma unroll
        for (int jp = 0; jp < 8; jp++) {
            ulonglong2 w = *reinterpret_cast<const ulonglong2*>(&sW[k * 16 + 2 * jp]);
            a[jp] = ffma2(a0, w.x, a[jp]);
            c[jp] = ffma2(a0, w.y, c[jp]);
            A[jp] = ffma2(a1, w.x, A[jp]);
            C[jp] = ffma2(a1, w.y, C[jp]);
        }
    }
#pragma unroll
    for (int jp = 0; jp < 8; jp++) {
        out0[2 * jp]     = pair_relu_h2(a[jp]);
        out0[2 * jp + 1] = pair_relu_h2(c[jp]);
        out1[2 * jp]     = pair_relu_h2(A[jp]);
        out1[2 * jp + 1] = pair_relu_h2(C[jp]);
    }
}

// First layer: 7 f32x2 inputs (coords + feat), 16 half2 outputs.
__device__ __forceinline__ void layer_first(const ull* __restrict__ sW,
                                            const ull* __restrict__ sB,
                                            const ull in0[7], const ull in1[7],
                                            __half2 out0[16], __half2 out1[16]) {
    ull a[8], c[8], A[8], C[8];
#pragma unroll
    for (int jp = 0; jp < 8; jp++) {
        ull b0 = sB[2 * jp], b1 = sB[2 * jp + 1];
        a[jp] = b0; c[jp] = b1;
        A[jp] = b0; C[jp] = b1;
    }
#pragma unroll
    for (int k = 0; k < 7; k++) {
        ull a0 = in0[k], a1 = in1[k];
#pragma unroll
        for (int jp = 0; jp < 8; jp++) {
            ulonglong2 w = *reinterpret_cast<const ulonglong2*>(&sW[k * 16 + 2 * jp]);
            a[jp] = ffma2(a0, w.x, a[jp]);
            c[jp] = ffma2(a0, w.y, c[jp]);
            A[jp] = ffma2(a1, w.x, A[jp]);
            C[jp] = ffma2(a1, w.y, C[jp]);
        }
    }
#pragma unroll
    for (int jp = 0; jp < 8; jp++) {
        out0[2 * jp]     = pair_relu_h2(a[jp]);
        out0[2 * jp + 1] = pair_relu_h2(c[jp]);
        out1[2 * jp]     = pair_relu_h2(A[jp]);
        out1[2 * jp + 1] = pair_relu_h2(C[jp]);
    }
}

// Final layer: 16 half2 in, 3 f32x2 out per pair-set (no relu).
__device__ __forceinline__ void layer_out_h(const ull* __restrict__ sW,
                                            const ull* __restrict__ sB,
                                            const __half2 in0[16],
                                            const __half2 in1[16],
                                            ull o0[3], ull o1[3]) {
#pragma unroll
    for (int j = 0; j < 3; j++) { o0[j] = sB[j]; o1[j] = sB[j]; }
#pragma unroll
    for (int k = 0; k < 16; k++) {
        ull a0 = h2_to_pair(in0[k]);
        ull a1 = h2_to_pair(in1[k]);
#pragma unroll
        for (int j = 0; j < 3; j++) {
            ull w = sW[k * 3 + j];
            o0[j] = ffma2(a0, w, o0[j]);
            o1[j] = ffma2(a1, w, o1[j]);
        }
    }
}

// ---------------------------------------------------------------------------
// Main fused kernel: 4 points per thread (2 f32x2 pair-sets).
// ---------------------------------------------------------------------------
__global__ __launch_bounds__(128, 4) void mlp_kernel(
    const float* __restrict__ x,
    const float* __restrict__ W1, const float* __restrict__ b1,
    const float* __restrict__ W2, const float* __restrict__ b2,
    const float* __restrict__ W3, const float* __restrict__ b3,
    const float* __restrict__ W4, const float* __restrict__ b4,
    const float* __restrict__ W5, const float* __restrict__ b5,
    float* __restrict__ out, int n)
{
    __shared__ alignas(16) ull sW1[7 * 16];
    __shared__ alignas(16) ull sW2[16 * 16];
    __shared__ alignas(16) ull sW3[16 * 16];
    __shared__ alignas(16) ull sW4[16 * 16];
    __shared__ alignas(16) ull sW5[16 * 3];
    __shared__ alignas(16) ull sB1[16], sB2[16], sB3[16], sB4[16], sB5[4];

    int tid = threadIdx.x;
    for (int i = tid; i < 112; i += 128) sW1[i] = pack2(W1[i], W1[i]);
    for (int i = tid; i < 256; i += 128) {
        sW2[i] = pack2(W2[i], W2[i]);
        sW3[i] = pack2(W3[i], W3[i]);
        sW4[i] = pack2(W4[i], W4[i]);
    }
    for (int i = tid; i < 48; i += 128) sW5[i] = pack2(W5[i], W5[i]);
    if (tid < 16) {
        sB1[tid] = pack2(b1[tid], b1[tid]);
        sB2[tid] = pack2(b2[tid], b2[tid]);
        sB3[tid] = pack2(b3[tid], b3[tid]);
        sB4[tid] = pack2(b4[tid], b4[tid]);
    }
    if (tid < 3) sB5[tid] = pack2(b5[tid], b5[tid]);
    __syncthreads();

    long base = (long)(blockIdx.x * 128 + tid) * 4;
    if (base >= n) return;

    // ---- load 4 points' coordinates ----
    float px[4], py[4], pz[4];
    if (base + 4 <= (long)n) {
        const float4* xv = reinterpret_cast<const float4*>(x + base * 3);
        float4 A = __ldg(xv), B = __ldg(xv + 1), C = __ldg(xv + 2);
        px[0] = A.x; py[0] = A.y; pz[0] = A.z;
        px[1] = A.w; py[1] = B.x; pz[1] = B.y;
        px[2] = B.z; py[2] = B.w; pz[2] = C.x;
        px[3] = C.y; py[3] = C.z; pz[3] = C.w;
    } else {
        float tmp[12];
        int cnt = (int)(n - base) * 3;
#pragma unroll
        for (int i = 0; i < 12; i++) tmp[i] = (i < cnt) ? x[base * 3 + i] : 0.0f;
#pragma unroll
        for (int p = 0; p < 4; p++) {
            px[p] = tmp[p * 3 + 0];
            py[p] = tmp[p * 3 + 1];
            pz[p] = tmp[p * 3 + 2];
        }
    }

    // ---- bilinear gather (2 x LDG.128 per point) ----
    float ft[4][4];
#pragma unroll
    for (int p = 0; p < 4; p++) sample_fm(px[p], py[p], ft[p]);

    // ---- first-layer inputs as f32x2 pairs ----
    ull u0[7], u1[7];
    u0[0] = pack2(px[0], px[1]);  u1[0] = pack2(px[2], px[3]);
    u0[1] = pack2(py[0], py[1]);  u1[1] = pack2(py[2], py[3]);
    u0[2] = pack2(pz[0], pz[1]);  u1[2] = pack2(pz[2], pz[3]);
#pragma unroll
    for (int c = 0; c < 4; c++) {
        u0[3 + c] = pack2(ft[0][c], ft[1][c]);
        u1[3 + c] = pack2(ft[2][c], ft[3][c]);
    }

    // ---- MLP (activations stored as half2 between layers) ----
    __half2 hA0[16], hA1[16], hB0[16], hB1[16];
    layer_first(sW1, sB1, u0, u1, hA0, hA1);
    layer_h16(sW2, sB2, hA0, hA1, hB0, hB1);
    layer_h16(sW3, sB3, hB0, hB1, hA0, hA1);
    layer_h16(sW4, sB4, hA0, hA1, hB0, hB1);

    ull o0[3], o1[3];
    layer_out_h(sW5, sB5, hB0, hB1, o0, o1);

    // ---- unpack + store 12 floats ----
    float r[12];
    unpack2(o0[0], r[0], r[3]);
    unpack2(o0[1], r[1], r[4]);
    unpack2(o0[2], r[2], r[5]);
    unpack2(o1[0], r[6], r[9]);
    unpack2(o1[1], r[7], r[10]);
    unpack2(o1[2], r[8], r[11]);

    if (base + 4 <= (long)n) {
        float4* ov = reinterpret_cast<float4*>(out + base * 3);
        ov[0] = make_float4(r[0], r[1], r[2], r[3]);
        ov[1] = make_float4(r[4], r[5], r[6], r[7]);
        ov[2] = make_float4(r[8], r[9], r[10], r[11]);
    } else {
        int cnt = (int)(n - base) * 3;
        for (int i = 0; i < cnt; i++) out[base * 3 + i] = r[i];
    }
}

// ---------------------------------------------------------------------------
// kernel_launch — graph-capturable, allocation-free.
// ---------------------------------------------------------------------------
extern "C" void kernel_launch(void* const* d_in, const int* in_sizes, int n_in,
                              void* d_out, int out_size) {
    const float* x  = (const float*)d_in[0];
    const float* fm = (const float*)d_in[1];
    const float* W1 = (const float*)d_in[2];
    const float* b1 = (const float*)d_in[3];
    const float* W2 = (const float*)d_in[4];
    const float* b2 = (const float*)d_in[5];
    const float* W3 = (const float*)d_in[6];
    const float* b3 = (const float*)d_in[7];
    const float* W4 = (const float*)d_in[8];
    const float* b4 = (const float*)d_in[9];
    const float* W5 = (const float*)d_in[10];
    const float* b5 = (const float*)d_in[11];

    int n = in_sizes[0] / 3;   // 4,000,000 points

    fm_pack_kernel<<<(512 * 512 + 255) / 256, 256>>>(fm);

    int nthreads = (n + 3) / 4;
    int nblocks  = (nthreads + 127) / 128;
    mlp_kernel<<<nblocks, 128>>>(x, W1, b1, W2, b2, W3, b3, W4, b4, W5, b5,
                                 (float*)d_out, n);
}

// round 11
// speedup vs baseline: 3.0030x; 2.8385x over previous
#include <cuda_runtime.h>
#include <cuda_fp16.h>
#include <cstdint>

// ---------------------------------------------------------------------------
// Device scratch: featuremap as fp16, x-pair duplicated. Entry (y,x) is 16B:
//   [ c0..c3 @(y,x) , c0..c3 @(y,min(x+1,511)) ]  as 8 halves.
// One LDG.128 fetches BOTH x-taps of one row -> 2 loads per bilinear sample.
// ---------------------------------------------------------------------------
__device__ uint4 g_fmH[512 * 512];

__global__ void fm_pack_kernel(const float* __restrict__ fm) {
    int i = blockIdx.x * blockDim.x + threadIdx.x;
    if (i >= 512 * 512) return;
    int x  = i & 511;
    int xn = min(x + 1, 511);
    int j  = i - x + xn;

    __half2 p01 = __floats2half2_rn(fm[i],              fm[i + 262144]);
    __half2 p23 = __floats2half2_rn(fm[i + 2 * 262144], fm[i + 3 * 262144]);
    __half2 q01 = __floats2half2_rn(fm[j],              fm[j + 262144]);
    __half2 q23 = __floats2half2_rn(fm[j + 2 * 262144], fm[j + 3 * 262144]);

    uint4 e;
    e.x = *reinterpret_cast<unsigned*>(&p01);
    e.y = *reinterpret_cast<unsigned*>(&p23);
    e.z = *reinterpret_cast<unsigned*>(&q01);
    e.w = *reinterpret_cast<unsigned*>(&q23);
    g_fmH[i] = e;
}

// ---------------------------------------------------------------------------
// helpers
// ---------------------------------------------------------------------------
__device__ __forceinline__ unsigned h2u(float a, float b) {
    __half2 h = __floats2half2_rn(a, b);
    return *reinterpret_cast<unsigned*>(&h);
}
__device__ __forceinline__ unsigned relu_h2u(float a, float b) {
    return h2u(fmaxf(a, 0.0f), fmaxf(b, 0.0f));
}

// m16n8k16 fp16 -> fp32
__device__ __forceinline__ void mma_16816(float d[4], const unsigned a[4],
                                          const unsigned b[2], const float c[4]) {
    asm volatile(
        "mma.sync.aligned.m16n8k16.row.col.f32.f16.f16.f32 "
        "{%0,%1,%2,%3}, {%4,%5,%6,%7}, {%8,%9}, {%10,%11,%12,%13};\n"
        : "=f"(d[0]), "=f"(d[1]), "=f"(d[2]), "=f"(d[3])
        : "r"(a[0]), "r"(a[1]), "r"(a[2]), "r"(a[3]),
          "r"(b[0]), "r"(b[1]),
          "f"(c[0]), "f"(c[1]), "f"(c[2]), "f"(c[3]));
}
// m16n8k8 fp16 -> fp32
__device__ __forceinline__ void mma_1688(float d[4], const unsigned a[2],
                                         unsigned b, const float c[4]) {
    asm volatile(
        "mma.sync.aligned.m16n8k8.row.col.f32.f16.f16.f32 "
        "{%0,%1,%2,%3}, {%4,%5}, {%6}, {%7,%8,%9,%10};\n"
        : "=f"(d[0]), "=f"(d[1]), "=f"(d[2]), "=f"(d[3])
        : "r"(a[0]), "r"(a[1]), "r"(b),
          "f"(c[0]), "f"(c[1]), "f"(c[2]), "f"(c[3]));
}

// hidden 16->16 layer on two m16 tiles, in-place on A fragments.
__device__ __forceinline__ void hidden16(unsigned A[2][4],
                                         const unsigned B[2][2],
                                         const float C[2][2]) {
#pragma unroll
    for (int T = 0; T < 2; T++) {
        float c0[4] = {C[0][0], C[0][1], C[0][0], C[0][1]};
        float c1[4] = {C[1][0], C[1][1], C[1][0], C[1][1]};
        float d0[4], d1[4];
        mma_16816(d0, A[T], B[0], c0);
        mma_16816(d1, A[T], B[1], c1);
        A[T][0] = relu_h2u(d0[0], d0[1]);
        A[T][1] = relu_h2u(d0[2], d0[3]);
        A[T][2] = relu_h2u(d1[0], d1[1]);
        A[T][3] = relu_h2u(d1[2], d1[3]);
    }
}

// ---------------------------------------------------------------------------
// Main kernel: 4 warps/block, each warp 8 iterations x 32 points = 256 pts,
// block = 1024 points. MLP runs on tensor cores via mma.sync fragments.
// ---------------------------------------------------------------------------
__global__ __launch_bounds__(128) void mlp_mma_kernel(
    const float* __restrict__ x,
    const float* __restrict__ W1, const float* __restrict__ b1,
    const float* __restrict__ W2, const float* __restrict__ b2,
    const float* __restrict__ W3, const float* __restrict__ b3,
    const float* __restrict__ W4, const float* __restrict__ b4,
    const float* __restrict__ W5, const float* __restrict__ b5,
    float* __restrict__ out, int n)
{
    __shared__ uint4 sIn[4][32];      // per-warp input rows (8 halves each)
    __shared__ float sOut[4][96];     // per-warp output staging (32 pts x 3)

    const int tid  = threadIdx.x;
    const int w    = tid >> 5;
    const int lane = tid & 31;
    const int g    = lane >> 2;       // 0..7
    const int q    = lane & 3;        // 0..3
    const int k0   = 2 * q;
    const int k1   = 2 * q + 1;

    // ---- per-thread weight/bias fragments (loaded once) ----
    unsigned B1f[2];        float C1f[2][2];
    unsigned B2f[2][2];     float C2f[2][2];
    unsigned B3f[2][2];     float C3f[2][2];
    unsigned B4f[2][2];     float C4f[2][2];
    unsigned B5f[2];        float C5f[2];

#pragma unroll
    for (int t = 0; t < 2; t++) {
        int nn = 8 * t + g;
        // layer1: W1 is [7][16]; pad k to 8 with zeros
        float w0 = (k0 < 7) ? __ldg(&W1[k0 * 16 + nn]) : 0.0f;
        float w1 = (k1 < 7) ? __ldg(&W1[k1 * 16 + nn]) : 0.0f;
        B1f[t] = h2u(w0, w1);
        C1f[t][0] = __ldg(&b1[8 * t + k0]);
        C1f[t][1] = __ldg(&b1[8 * t + k1]);

        B2f[t][0] = h2u(__ldg(&W2[k0 * 16 + nn]),       __ldg(&W2[k1 * 16 + nn]));
        B2f[t][1] = h2u(__ldg(&W2[(k0 + 8) * 16 + nn]), __ldg(&W2[(k1 + 8) * 16 + nn]));
        C2f[t][0] = __ldg(&b2[8 * t + k0]);
        C2f[t][1] = __ldg(&b2[8 * t + k1]);

        B3f[t][0] = h2u(__ldg(&W3[k0 * 16 + nn]),       __ldg(&W3[k1 * 16 + nn]));
        B3f[t][1] = h2u(__ldg(&W3[(k0 + 8) * 16 + nn]), __ldg(&W3[(k1 + 8) * 16 + nn]));
        C3f[t][0] = __ldg(&b3[8 * t + k0]);
        C3f[t][1] = __ldg(&b3[8 * t + k1]);

        B4f[t][0] = h2u(__ldg(&W4[k0 * 16 + nn]),       __ldg(&W4[k1 * 16 + nn]));
        B4f[t][1] = h2u(__ldg(&W4[(k0 + 8) * 16 + nn]), __ldg(&W4[(k1 + 8) * 16 + nn]));
        C4f[t][0] = __ldg(&b4[8 * t + k0]);
        C4f[t][1] = __ldg(&b4[8 * t + k1]);
    }
    // layer5: W5 is [16][3]; pad n to 8 with zeros. single n-tile (t=0).
    {
        float w50 = (g < 3) ? __ldg(&W5[k0 * 3 + g]) : 0.0f;
        float w51 = (g < 3) ? __ldg(&W5[k1 * 3 + g]) : 0.0f;
        float w52 = (g < 3) ? __ldg(&W5[(k0 + 8) * 3 + g]) : 0.0f;
        float w53 = (g < 3) ? __ldg(&W5[(k1 + 8) * 3 + g]) : 0.0f;
        B5f[0] = h2u(w50, w51);
        B5f[1] = h2u(w52, w53);
        C5f[0] = (k0 < 3) ? __ldg(&b5[k0]) : 0.0f;
        C5f[1] = (k1 < 3) ? __ldg(&b5[k1]) : 0.0f;
    }

    const long warpbase = (long)blockIdx.x * 1024 + w * 256;

    for (int it = 0; it < 8; it++) {
        long pbase = warpbase + (long)it * 32;
        if (pbase >= n) break;                 // warp-uniform
        long p = pbase + lane;

        // ---- load coords ----
        float u = 0.0f, v = 0.0f, zc = 0.0f;
        if (p < (long)n) {
            u  = __ldg(&x[p * 3 + 0]);
            v  = __ldg(&x[p * 3 + 1]);
            zc = __ldg(&x[p * 3 + 2]);
        }

        // ---- bilinear gather (border clamp; identical math to reference) ----
        float fx = fminf(fmaxf(fmaf(u, 512.0f, -0.5f), 0.0f), 511.0f);
        float fy = fminf(fmaxf(fmaf(v, 512.0f, -0.5f), 0.0f), 511.0f);
        float x0f = floorf(fx), y0f = floorf(fy);
        float wx = fx - x0f, wy = fy - y0f;
        int ix0 = (int)x0f, iy0 = (int)y0f;
        int iy1 = min(iy0 + 1, 511);

        uint4 r0 = __ldg(&g_fmH[iy0 * 512 + ix0]);
        uint4 r1 = __ldg(&g_fmH[iy1 * 512 + ix0]);

        float f[4];
        {
            float2 a01 = __half22float2(*reinterpret_cast<__half2*>(&r0.x));
            float2 a23 = __half22float2(*reinterpret_cast<__half2*>(&r0.y));
            float2 b01 = __half22float2(*reinterpret_cast<__half2*>(&r0.z));
            float2 b23 = __half22float2(*reinterpret_cast<__half2*>(&r0.w));
            float2 c01 = __half22float2(*reinterpret_cast<__half2*>(&r1.x));
            float2 c23 = __half22float2(*reinterpret_cast<__half2*>(&r1.y));
            float2 d01 = __half22float2(*reinterpret_cast<__half2*>(&r1.z));
            float2 d23 = __half22float2(*reinterpret_cast<__half2*>(&r1.w));
            float t0, t1;
            t0 = fmaf(wx, b01.x - a01.x, a01.x);
            t1 = fmaf(wx, d01.x - c01.x, c01.x);
            f[0] = fmaf(wy, t1 - t0, t0);
            t0 = fmaf(wx, b01.y - a01.y, a01.y);
            t1 = fmaf(wx, d01.y - c01.y, c01.y);
            f[1] = fmaf(wy, t1 - t0, t0);
            t0 = fmaf(wx, b23.x - a23.x, a23.x);
            t1 = fmaf(wx, d23.x - c23.x, c23.x);
            f[2] = fmaf(wy, t1 - t0, t0);
            t0 = fmaf(wx, b23.y - a23.y, a23.y);
            t1 = fmaf(wx, d23.y - c23.y, c23.y);
            f[3] = fmaf(wy, t1 - t0, t0);
        }

        // ---- stage input row: [x,y,z,f0,f1,f2,f3,0] as 8 halves ----
        uint4 row;
        row.x = h2u(u, v);
        row.y = h2u(zc, f[0]);
        row.z = h2u(f[1], f[2]);
        row.w = h2u(f[3], 0.0f);
        sIn[w][lane] = row;
        __syncwarp();

        // ---- ldmatrix x4: two m16k8 A fragments (tiles of 16 points) ----
        unsigned a0, a1, a2, a3;
        unsigned addr = (unsigned)__cvta_generic_to_shared(&sIn[w][lane]);
        asm volatile(
            "ldmatrix.sync.aligned.m8n8.x4.shared.b16 {%0,%1,%2,%3}, [%4];\n"
            : "=r"(a0), "=r"(a1), "=r"(a2), "=r"(a3)
            : "r"(addr));
        __syncwarp();   // sIn reusable next iteration

        // ---- layer 1 (k=8) ----
        unsigned A[2][4];
        {
            unsigned A1[2][2] = {{a0, a1}, {a2, a3}};
#pragma unroll
            for (int T = 0; T < 2; T++) {
                float c0[4] = {C1f[0][0], C1f[0][1], C1f[0][0], C1f[0][1]};
                float c1[4] = {C1f[1][0], C1f[1][1], C1f[1][0], C1f[1][1]};
                float d0[4], d1[4];
                mma_1688(d0, A1[T], B1f[0], c0);
                mma_1688(d1, A1[T], B1f[1], c1);
                A[T][0] = relu_h2u(d0[0], d0[1]);
                A[T][1] = relu_h2u(d0[2], d0[3]);
                A[T][2] = relu_h2u(d1[0], d1[1]);
                A[T][3] = relu_h2u(d1[2], d1[3]);
            }
        }

        // ---- layers 2-4 ----
        hidden16(A, B2f, C2f);
        hidden16(A, B3f, C3f);
        hidden16(A, B4f, C4f);

        // ---- layer 5 (n=3 padded to 8, single n-tile) ----
        float d5[2][4];
#pragma unroll
        for (int T = 0; T < 2; T++) {
            float c[4] = {C5f[0], C5f[1], C5f[0], C5f[1]};
            mma_16816(d5[T], A[T], B5f, c);
        }

        // ---- stage outputs: point row = T*16 + (g | g+8), cols 2q, 2q+1 ----
        if (q == 0) {
#pragma unroll
            for (int T = 0; T < 2; T++) {
                sOut[w][(T * 16 + g) * 3 + 0]     = d5[T][0];
                sOut[w][(T * 16 + g) * 3 + 1]     = d5[T][1];
                sOut[w][(T * 16 + g + 8) * 3 + 0] = d5[T][2];
                sOut[w][(T * 16 + g + 8) * 3 + 1] = d5[T][3];
            }
        } else if (q == 1) {
#pragma unroll
            for (int T = 0; T < 2; T++) {
                sOut[w][(T * 16 + g) * 3 + 2]     = d5[T][0];
                sOut[w][(T * 16 + g + 8) * 3 + 2] = d5[T][2];
            }
        }
        __syncwarp();

        // ---- store 96 contiguous floats ----
        if (pbase + 32 <= (long)n) {
            float4* dst = reinterpret_cast<float4*>(out + pbase * 3);
            const float4* src = reinterpret_cast<const float4*>(sOut[w]);
            if (lane < 24) dst[lane] = src[lane];
        } else {
            int cnt = (int)(n - pbase) * 3;
            for (int idx = lane; idx < cnt; idx += 32)
                out[pbase * 3 + idx] = sOut[w][idx];
        }
        __syncwarp();
    }
}

// ---------------------------------------------------------------------------
// kernel_launch — graph-capturable, allocation-free.
// ---------------------------------------------------------------------------
extern "C" void kernel_launch(void* const* d_in, const int* in_sizes, int n_in,
                              void* d_out, int out_size) {
    const float* x  = (const float*)d_in[0];
    const float* fm = (const float*)d_in[1];
    const float* W1 = (const float*)d_in[2];
    const float* b1 = (const float*)d_in[3];
    const float* W2 = (const float*)d_in[4];
    const float* b2 = (const float*)d_in[5];
    const float* W3 = (const float*)d_in[6];
    const float* b3 = (const float*)d_in[7];
    const float* W4 = (const float*)d_in[8];
    const float* b4 = (const float*)d_in[9];
    const float* W5 = (const float*)d_in[10];
    const float* b5 = (const float*)d_in[11];

    int n = in_sizes[0] / 3;   // 4,000,000 points

    fm_pack_kernel<<<(512 * 512 + 255) / 256, 256>>>(fm);

    int nblocks = (n + 1023) / 1024;   // 1024 points per block
    mlp_mma_kernel<<<nblocks, 128>>>(x, W1, b1, W2, b2, W3, b3, W4, b4, W5, b5,
                                     (float*)d_out, n);
}

// round 12
// speedup vs baseline: 3.0134x; 1.0034x over previous
#include <cuda_runtime.h>
#include <cuda_fp16.h>
#include <cstdint>

// ---------------------------------------------------------------------------
// Device scratch: featuremap as fp16, x-pair duplicated. Entry (y,x) is 16B:
//   [ c0..c3 @(y,x) , c0..c3 @(y,min(x+1,511)) ]  as 8 halves.
// One LDG.128 fetches BOTH x-taps of one row -> 2 loads per bilinear sample.
// ---------------------------------------------------------------------------
__device__ uint4 g_fmH[512 * 512];

__global__ void fm_pack_kernel(const float* __restrict__ fm) {
    int i = blockIdx.x * blockDim.x + threadIdx.x;
    if (i >= 512 * 512) return;
    int x  = i & 511;
    int xn = min(x + 1, 511);
    int j  = i - x + xn;

    __half2 p01 = __floats2half2_rn(fm[i],              fm[i + 262144]);
    __half2 p23 = __floats2half2_rn(fm[i + 2 * 262144], fm[i + 3 * 262144]);
    __half2 q01 = __floats2half2_rn(fm[j],              fm[j + 262144]);
    __half2 q23 = __floats2half2_rn(fm[j + 2 * 262144], fm[j + 3 * 262144]);

    uint4 e;
    e.x = *reinterpret_cast<unsigned*>(&p01);
    e.y = *reinterpret_cast<unsigned*>(&p23);
    e.z = *reinterpret_cast<unsigned*>(&q01);
    e.w = *reinterpret_cast<unsigned*>(&q23);
    g_fmH[i] = e;
}

// ---------------------------------------------------------------------------
// helpers
// ---------------------------------------------------------------------------
__device__ __forceinline__ unsigned h2u(float a, float b) {
    __half2 h = __floats2half2_rn(a, b);
    return *reinterpret_cast<unsigned*>(&h);
}
__device__ __forceinline__ unsigned relu_h2u(float a, float b) {
    return h2u(fmaxf(a, 0.0f), fmaxf(b, 0.0f));
}

// m16n8k16 fp16 -> fp32
__device__ __forceinline__ void mma_16816(float d[4], const unsigned a[4],
                                          const unsigned b[2], const float c[4]) {
    asm volatile(
        "mma.sync.aligned.m16n8k16.row.col.f32.f16.f16.f32 "
        "{%0,%1,%2,%3}, {%4,%5,%6,%7}, {%8,%9}, {%10,%11,%12,%13};\n"
        : "=f"(d[0]), "=f"(d[1]), "=f"(d[2]), "=f"(d[3])
        : "r"(a[0]), "r"(a[1]), "r"(a[2]), "r"(a[3]),
          "r"(b[0]), "r"(b[1]),
          "f"(c[0]), "f"(c[1]), "f"(c[2]), "f"(c[3]));
}
// m16n8k8 fp16 -> fp32
__device__ __forceinline__ void mma_1688(float d[4], const unsigned a[2],
                                         unsigned b, const float c[4]) {
    asm volatile(
        "mma.sync.aligned.m16n8k8.row.col.f32.f16.f16.f32 "
        "{%0,%1,%2,%3}, {%4,%5}, {%6}, {%7,%8,%9,%10};\n"
        : "=f"(d[0]), "=f"(d[1]), "=f"(d[2]), "=f"(d[3])
        : "r"(a[0]), "r"(a[1]), "r"(b),
          "f"(c[0]), "f"(c[1]), "f"(c[2]), "f"(c[3]));
}

// hidden 16->16 layer on two m16 tiles, in-place on A fragments.
__device__ __forceinline__ void hidden16(unsigned A[2][4],
                                         const unsigned B[2][2],
                                         const float C[2][2]) {
#pragma unroll
    for (int T = 0; T < 2; T++) {
        float c0[4] = {C[0][0], C[0][1], C[0][0], C[0][1]};
        float c1[4] = {C[1][0], C[1][1], C[1][0], C[1][1]};
        float d0[4], d1[4];
        mma_16816(d0, A[T], B[0], c0);
        mma_16816(d1, A[T], B[1], c1);
        A[T][0] = relu_h2u(d0[0], d0[1]);
        A[T][1] = relu_h2u(d0[2], d0[3]);
        A[T][2] = relu_h2u(d1[0], d1[1]);
        A[T][3] = relu_h2u(d1[2], d1[3]);
    }
}

// ---------------------------------------------------------------------------
// Main kernel: 4 warps/block, each warp 8 iterations x 32 points = 256 pts,
// block = 1024 points. MLP runs on tensor cores via mma.sync fragments.
// ---------------------------------------------------------------------------
__global__ __launch_bounds__(128) void mlp_mma_kernel(
    const float* __restrict__ x,
    const float* __restrict__ W1, const float* __restrict__ b1,
    const float* __restrict__ W2, const float* __restrict__ b2,
    const float* __restrict__ W3, const float* __restrict__ b3,
    const float* __restrict__ W4, const float* __restrict__ b4,
    const float* __restrict__ W5, const float* __restrict__ b5,
    float* __restrict__ out, int n)
{
    __shared__ uint4 sIn[4][32];      // per-warp input rows (8 halves each)
    __shared__ float sOut[4][96];     // per-warp output staging (32 pts x 3)

    const int tid  = threadIdx.x;
    const int w    = tid >> 5;
    const int lane = tid & 31;
    const int g    = lane >> 2;       // 0..7
    const int q    = lane & 3;        // 0..3
    const int k0   = 2 * q;
    const int k1   = 2 * q + 1;

    // ---- per-thread weight/bias fragments (loaded once) ----
    unsigned B1f[2];        float C1f[2][2];
    unsigned B2f[2][2];     float C2f[2][2];
    unsigned B3f[2][2];     float C3f[2][2];
    unsigned B4f[2][2];     float C4f[2][2];
    unsigned B5f[2];        float C5f[2];

#pragma unroll
    for (int t = 0; t < 2; t++) {
        int nn = 8 * t + g;
        // layer1: W1 is [7][16]; pad k to 8 with zeros
        float w0 = (k0 < 7) ? __ldg(&W1[k0 * 16 + nn]) : 0.0f;
        float w1 = (k1 < 7) ? __ldg(&W1[k1 * 16 + nn]) : 0.0f;
        B1f[t] = h2u(w0, w1);
        C1f[t][0] = __ldg(&b1[8 * t + k0]);
        C1f[t][1] = __ldg(&b1[8 * t + k1]);

        B2f[t][0] = h2u(__ldg(&W2[k0 * 16 + nn]),       __ldg(&W2[k1 * 16 + nn]));
        B2f[t][1] = h2u(__ldg(&W2[(k0 + 8) * 16 + nn]), __ldg(&W2[(k1 + 8) * 16 + nn]));
        C2f[t][0] = __ldg(&b2[8 * t + k0]);
        C2f[t][1] = __ldg(&b2[8 * t + k1]);

        B3f[t][0] = h2u(__ldg(&W3[k0 * 16 + nn]),       __ldg(&W3[k1 * 16 + nn]));
        B3f[t][1] = h2u(__ldg(&W3[(k0 + 8) * 16 + nn]), __ldg(&W3[(k1 + 8) * 16 + nn]));
        C3f[t][0] = __ldg(&b3[8 * t + k0]);
        C3f[t][1] = __ldg(&b3[8 * t + k1]);

        B4f[t][0] = h2u(__ldg(&W4[k0 * 16 + nn]),       __ldg(&W4[k1 * 16 + nn]));
        B4f[t][1] = h2u(__ldg(&W4[(k0 + 8) * 16 + nn]), __ldg(&W4[(k1 + 8) * 16 + nn]));
        C4f[t][0] = __ldg(&b4[8 * t + k0]);
        C4f[t][1] = __ldg(&b4[8 * t + k1]);
    }
    // layer5: W5 is [16][3]; pad n to 8 with zeros. single n-tile (t=0).
    {
        float w50 = (g < 3) ? __ldg(&W5[k0 * 3 + g]) : 0.0f;
        float w51 = (g < 3) ? __ldg(&W5[k1 * 3 + g]) : 0.0f;
        float w52 = (g < 3) ? __ldg(&W5[(k0 + 8) * 3 + g]) : 0.0f;
        float w53 = (g < 3) ? __ldg(&W5[(k1 + 8) * 3 + g]) : 0.0f;
        B5f[0] = h2u(w50, w51);
        B5f[1] = h2u(w52, w53);
        C5f[0] = (k0 < 3) ? __ldg(&b5[k0]) : 0.0f;
        C5f[1] = (k1 < 3) ? __ldg(&b5[k1]) : 0.0f;
    }

    const long warpbase = (long)blockIdx.x * 1024 + w * 256;

    for (int it = 0; it < 8; it++) {
        long pbase = warpbase + (long)it * 32;
        if (pbase >= n) break;                 // warp-uniform
        long p = pbase + lane;

        // ---- load coords ----
        float u = 0.0f, v = 0.0f, zc = 0.0f;
        if (p < (long)n) {
            u  = __ldg(&x[p * 3 + 0]);
            v  = __ldg(&x[p * 3 + 1]);
            zc = __ldg(&x[p * 3 + 2]);
        }

        // ---- bilinear gather (border clamp; identical math to reference) ----
        float fx = fminf(fmaxf(fmaf(u, 512.0f, -0.5f), 0.0f), 511.0f);
        float fy = fminf(fmaxf(fmaf(v, 512.0f, -0.5f), 0.0f), 511.0f);
        float x0f = floorf(fx), y0f = floorf(fy);
        float wx = fx - x0f, wy = fy - y0f;
        int ix0 = (int)x0f, iy0 = (int)y0f;
        int iy1 = min(iy0 + 1, 511);

        uint4 r0 = __ldg(&g_fmH[iy0 * 512 + ix0]);
        uint4 r1 = __ldg(&g_fmH[iy1 * 512 + ix0]);

        float f[4];
        {
            float2 a01 = __half22float2(*reinterpret_cast<__half2*>(&r0.x));
            float2 a23 = __half22float2(*reinterpret_cast<__half2*>(&r0.y));
            float2 b01 = __half22float2(*reinterpret_cast<__half2*>(&r0.z));
            float2 b23 = __half22float2(*reinterpret_cast<__half2*>(&r0.w));
            float2 c01 = __half22float2(*reinterpret_cast<__half2*>(&r1.x));
            float2 c23 = __half22float2(*reinterpret_cast<__half2*>(&r1.y));
            float2 d01 = __half22float2(*reinterpret_cast<__half2*>(&r1.z));
            float2 d23 = __half22float2(*reinterpret_cast<__half2*>(&r1.w));
            float t0, t1;
            t0 = fmaf(wx, b01.x - a01.x, a01.x);
            t1 = fmaf(wx, d01.x - c01.x, c01.x);
            f[0] = fmaf(wy, t1 - t0, t0);
            t0 = fmaf(wx, b01.y - a01.y, a01.y);
            t1 = fmaf(wx, d01.y - c01.y, c01.y);
            f[1] = fmaf(wy, t1 - t0, t0);
            t0 = fmaf(wx, b23.x - a23.x, a23.x);
            t1 = fmaf(wx, d23.x - c23.x, c23.x);
            f[2] = fmaf(wy, t1 - t0, t0);
            t0 = fmaf(wx, b23.y - a23.y, a23.y);
            t1 = fmaf(wx, d23.y - c23.y, c23.y);
            f[3] = fmaf(wy, t1 - t0, t0);
        }

        // ---- stage input row: [x,y,z,f0,f1,f2,f3,0] as 8 halves ----
        uint4 row;
        row.x = h2u(u, v);
        row.y = h2u(zc, f[0]);
        row.z = h2u(f[1], f[2]);
        row.w = h2u(f[3], 0.0f);
        sIn[w][lane] = row;
        __syncwarp();

        // ---- ldmatrix x4: two m16k8 A fragments (tiles of 16 points) ----
        unsigned a0, a1, a2, a3;
        unsigned addr = (unsigned)__cvta_generic_to_shared(&sIn[w][lane]);
        asm volatile(
            "ldmatrix.sync.aligned.m8n8.x4.shared.b16 {%0,%1,%2,%3}, [%4];\n"
            : "=r"(a0), "=r"(a1), "=r"(a2), "=r"(a3)
            : "r"(addr));
        __syncwarp();   // sIn reusable next iteration

        // ---- layer 1 (k=8) ----
        unsigned A[2][4];
        {
            unsigned A1[2][2] = {{a0, a1}, {a2, a3}};
#pragma unroll
            for (int T = 0; T < 2; T++) {
                float c0[4] = {C1f[0][0], C1f[0][1], C1f[0][0], C1f[0][1]};
                float c1[4] = {C1f[1][0], C1f[1][1], C1f[1][0], C1f[1][1]};
                float d0[4], d1[4];
                mma_1688(d0, A1[T], B1f[0], c0);
                mma_1688(d1, A1[T], B1f[1], c1);
                A[T][0] = relu_h2u(d0[0], d0[1]);
                A[T][1] = relu_h2u(d0[2], d0[3]);
                A[T][2] = relu_h2u(d1[0], d1[1]);
                A[T][3] = relu_h2u(d1[2], d1[3]);
            }
        }

        // ---- layers 2-4 ----
        hidden16(A, B2f, C2f);
        hidden16(A, B3f, C3f);
        hidden16(A, B4f, C4f);

        // ---- layer 5 (n=3 padded to 8, single n-tile) ----
        float d5[2][4];
#pragma unroll
        for (int T = 0; T < 2; T++) {
            float c[4] = {C5f[0], C5f[1], C5f[0], C5f[1]};
            mma_16816(d5[T], A[T], B5f, c);
        }

        // ---- stage outputs: point row = T*16 + (g | g+8), cols 2q, 2q+1 ----
        if (q == 0) {
#pragma unroll
            for (int T = 0; T < 2; T++) {
                sOut[w][(T * 16 + g) * 3 + 0]     = d5[T][0];
                sOut[w][(T * 16 + g) * 3 + 1]     = d5[T][1];
                sOut[w][(T * 16 + g + 8) * 3 + 0] = d5[T][2];
                sOut[w][(T * 16 + g + 8) * 3 + 1] = d5[T][3];
            }
        } else if (q == 1) {
#pragma unroll
            for (int T = 0; T < 2; T++) {
                sOut[w][(T * 16 + g) * 3 + 2]     = d5[T][0];
                sOut[w][(T * 16 + g + 8) * 3 + 2] = d5[T][2];
            }
        }
        __syncwarp();

        // ---- store 96 contiguous floats ----
        if (pbase + 32 <= (long)n) {
            float4* dst = reinterpret_cast<float4*>(out + pbase * 3);
            const float4* src = reinterpret_cast<const float4*>(sOut[w]);
            if (lane < 24) dst[lane] = src[lane];
        } else {
            int cnt = (int)(n - pbase) * 3;
            for (int idx = lane; idx < cnt; idx += 32)
                out[pbase * 3 + idx] = sOut[w][idx];
        }
        __syncwarp();
    }
}

// ---------------------------------------------------------------------------
// kernel_launch — graph-capturable, allocation-free.
// ---------------------------------------------------------------------------
extern "C" void kernel_launch(void* const* d_in, const int* in_sizes, int n_in,
                              void* d_out, int out_size) {
    const float* x  = (const float*)d_in[0];
    const float* fm = (const float*)d_in[1];
    const float* W1 = (const float*)d_in[2];
    const float* b1 = (const float*)d_in[3];
    const float* W2 = (const float*)d_in[4];
    const float* b2 = (const float*)d_in[5];
    const float* W3 = (const float*)d_in[6];
    const float* b3 = (const float*)d_in[7];
    const float* W4 = (const float*)d_in[8];
    const float* b4 = (const float*)d_in[9];
    const float* W5 = (const float*)d_in[10];
    const float* b5 = (const float*)d_in[11];

    int n = in_sizes[0] / 3;   // 4,000,000 points

    fm_pack_kernel<<<(512 * 512 + 255) / 256, 256>>>(fm);

    int nblocks = (n + 1023) / 1024;   // 1024 points per block
    mlp_mma_kernel<<<nblocks, 128>>>(x, W1, b1, W2, b2, W3, b3, W4, b4, W5, b5,
                                     (float*)d_out, n);
}

// round 13
// speedup vs baseline: 3.4816x; 1.1554x over previous
#include <cuda_runtime.h>
#include <cuda_fp16.h>
#include <cstdint>

// ---------------------------------------------------------------------------
// Device scratch: featuremap as fp16, x-pair duplicated. Entry (y,x) is 16B:
//   [ c0..c3 @(y,x) , c0..c3 @(y,min(x+1,511)) ]  as 8 halves.
// One LDG.128 fetches BOTH x-taps of one row -> 2 loads per bilinear sample.
// ---------------------------------------------------------------------------
__device__ uint4 g_fmH[512 * 512];

__global__ void fm_pack_kernel(const float* __restrict__ fm) {
    int i = blockIdx.x * blockDim.x + threadIdx.x;
    if (i >= 512 * 512) return;
    int x  = i & 511;
    int xn = min(x + 1, 511);
    int j  = i - x + xn;

    __half2 p01 = __floats2half2_rn(fm[i],              fm[i + 262144]);
    __half2 p23 = __floats2half2_rn(fm[i + 2 * 262144], fm[i + 3 * 262144]);
    __half2 q01 = __floats2half2_rn(fm[j],              fm[j + 262144]);
    __half2 q23 = __floats2half2_rn(fm[j + 2 * 262144], fm[j + 3 * 262144]);

    uint4 e;
    e.x = *reinterpret_cast<unsigned*>(&p01);
    e.y = *reinterpret_cast<unsigned*>(&p23);
    e.z = *reinterpret_cast<unsigned*>(&q01);
    e.w = *reinterpret_cast<unsigned*>(&q23);
    g_fmH[i] = e;
}

// ---------------------------------------------------------------------------
// helpers
// ---------------------------------------------------------------------------
__device__ __forceinline__ unsigned h2u(float a, float b) {
    __half2 h = __floats2half2_rn(a, b);
    return *reinterpret_cast<unsigned*>(&h);
}
__device__ __forceinline__ unsigned relu_pack(float a, float b) {
    __half2 h = __floats2half2_rn(a, b);
    h = __hmax2(h, __floats2half2_rn(0.0f, 0.0f));
    return *reinterpret_cast<unsigned*>(&h);
}
__device__ __forceinline__ __half2 u2h(unsigned u) {
    return *reinterpret_cast<__half2*>(&u);
}

// m16n8k16 fp16 -> fp32
__device__ __forceinline__ void mma_16816(float d[4], const unsigned a[4],
                                          const unsigned b[2], const float c[4]) {
    asm volatile(
        "mma.sync.aligned.m16n8k16.row.col.f32.f16.f16.f32 "
        "{%0,%1,%2,%3}, {%4,%5,%6,%7}, {%8,%9}, {%10,%11,%12,%13};\n"
        : "=f"(d[0]), "=f"(d[1]), "=f"(d[2]), "=f"(d[3])
        : "r"(a[0]), "r"(a[1]), "r"(a[2]), "r"(a[3]),
          "r"(b[0]), "r"(b[1]),
          "f"(c[0]), "f"(c[1]), "f"(c[2]), "f"(c[3]));
}
// m16n8k8 fp16 -> fp32
__device__ __forceinline__ void mma_1688(float d[4], const unsigned a[2],
                                         unsigned b, const float c[4]) {
    asm volatile(
        "mma.sync.aligned.m16n8k8.row.col.f32.f16.f16.f32 "
        "{%0,%1,%2,%3}, {%4,%5}, {%6}, {%7,%8,%9,%10};\n"
        : "=f"(d[0]), "=f"(d[1]), "=f"(d[2]), "=f"(d[3])
        : "r"(a[0]), "r"(a[1]), "r"(b),
          "f"(c[0]), "f"(c[1]), "f"(c[2]), "f"(c[3]));
}

// hidden 16->16 layer on two m16 tiles, in-place on A fragments.
__device__ __forceinline__ void hidden16(unsigned A[2][4],
                                         const unsigned B[2][2],
                                         const float C[2][2]) {
#pragma unroll
    for (int T = 0; T < 2; T++) {
        float c0[4] = {C[0][0], C[0][1], C[0][0], C[0][1]};
        float c1[4] = {C[1][0], C[1][1], C[1][0], C[1][1]};
        float d0[4], d1[4];
        mma_16816(d0, A[T], B[0], c0);
        mma_16816(d1, A[T], B[1], c1);
        A[T][0] = relu_pack(d0[0], d0[1]);
        A[T][1] = relu_pack(d0[2], d0[3]);
        A[T][2] = relu_pack(d1[0], d1[1]);
        A[T][3] = relu_pack(d1[2], d1[3]);
    }
}

// issue gather loads for one point; results + packed (wx,wy) carried in regs
__device__ __forceinline__ void issue_gather(float u, float v,
                                             uint4& r0, uint4& r1,
                                             unsigned& wxy) {
    float fx = fminf(fmaxf(fmaf(u, 512.0f, -0.5f), 0.0f), 511.0f);
    float fy = fminf(fmaxf(fmaf(v, 512.0f, -0.5f), 0.0f), 511.0f);
    float x0f = floorf(fx), y0f = floorf(fy);
    wxy = h2u(fx - x0f, fy - y0f);
    int ix0 = (int)x0f, iy0 = (int)y0f;
    int iy1 = min(iy0 + 1, 511);
    r0 = __ldg(&g_fmH[iy0 * 512 + ix0]);
    r1 = __ldg(&g_fmH[iy1 * 512 + ix0]);
}

// ---------------------------------------------------------------------------
// Main kernel: 4 warps/block, each warp 8 iterations x 32 points = 256 pts.
// Coords prefetched 2 iterations ahead, gathers 1 iteration ahead.
// ---------------------------------------------------------------------------
__global__ __launch_bounds__(128) void mlp_mma_kernel(
    const float* __restrict__ x,
    const float* __restrict__ W1, const float* __restrict__ b1,
    const float* __restrict__ W2, const float* __restrict__ b2,
    const float* __restrict__ W3, const float* __restrict__ b3,
    const float* __restrict__ W4, const float* __restrict__ b4,
    const float* __restrict__ W5, const float* __restrict__ b5,
    float* __restrict__ out, int n)
{
    __shared__ uint4 sIn[4][32];      // per-warp input rows (8 halves each)
    __shared__ float sOut[4][96];     // per-warp output staging (32 pts x 3)

    const int tid  = threadIdx.x;
    const int w    = tid >> 5;
    const int lane = tid & 31;
    const int g    = lane >> 2;       // 0..7
    const int q    = lane & 3;        // 0..3
    const int k0   = 2 * q;
    const int k1   = 2 * q + 1;

    // ---- per-thread weight/bias fragments (loaded once) ----
    // input row layout: [x, y, z, 0, f0, f1, f2, f3]  (pad at k=3)
    unsigned B1f[2];        float C1f[2][2];
    unsigned B2f[2][2];     float C2f[2][2];
    unsigned B3f[2][2];     float C3f[2][2];
    unsigned B4f[2][2];     float C4f[2][2];
    unsigned B5f[2];        float C5f[2];

#pragma unroll
    for (int t = 0; t < 2; t++) {
        int nn = 8 * t + g;
        // layer1 with reordered k: k<3 -> W1 row k, k==3 -> 0, k>3 -> W1 row k-1
        float w0 = (k0 < 3) ? __ldg(&W1[k0 * 16 + nn])
                            : ((k0 == 3) ? 0.0f : __ldg(&W1[(k0 - 1) * 16 + nn]));
        float w1 = (k1 < 3) ? __ldg(&W1[k1 * 16 + nn])
                            : ((k1 == 3) ? 0.0f : __ldg(&W1[(k1 - 1) * 16 + nn]));
        B1f[t] = h2u(w0, w1);
        C1f[t][0] = __ldg(&b1[8 * t + k0]);
        C1f[t][1] = __ldg(&b1[8 * t + k1]);

        B2f[t][0] = h2u(__ldg(&W2[k0 * 16 + nn]),       __ldg(&W2[k1 * 16 + nn]));
        B2f[t][1] = h2u(__ldg(&W2[(k0 + 8) * 16 + nn]), __ldg(&W2[(k1 + 8) * 16 + nn]));
        C2f[t][0] = __ldg(&b2[8 * t + k0]);
        C2f[t][1] = __ldg(&b2[8 * t + k1]);

        B3f[t][0] = h2u(__ldg(&W3[k0 * 16 + nn]),       __ldg(&W3[k1 * 16 + nn]));
        B3f[t][1] = h2u(__ldg(&W3[(k0 + 8) * 16 + nn]), __ldg(&W3[(k1 + 8) * 16 + nn]));
        C3f[t][0] = __ldg(&b3[8 * t + k0]);
        C3f[t][1] = __ldg(&b3[8 * t + k1]);

        B4f[t][0] = h2u(__ldg(&W4[k0 * 16 + nn]),       __ldg(&W4[k1 * 16 + nn]));
        B4f[t][1] = h2u(__ldg(&W4[(k0 + 8) * 16 + nn]), __ldg(&W4[(k1 + 8) * 16 + nn]));
        C4f[t][0] = __ldg(&b4[8 * t + k0]);
        C4f[t][1] = __ldg(&b4[8 * t + k1]);
    }
    // layer5: W5 is [16][3]; pad n to 8 with zeros. single n-tile.
    {
        float w50 = (g < 3) ? __ldg(&W5[k0 * 3 + g]) : 0.0f;
        float w51 = (g < 3) ? __ldg(&W5[k1 * 3 + g]) : 0.0f;
        float w52 = (g < 3) ? __ldg(&W5[(k0 + 8) * 3 + g]) : 0.0f;
        float w53 = (g < 3) ? __ldg(&W5[(k1 + 8) * 3 + g]) : 0.0f;
        B5f[0] = h2u(w50, w51);
        B5f[1] = h2u(w52, w53);
        C5f[0] = (k0 < 3) ? __ldg(&b5[k0]) : 0.0f;
        C5f[1] = (k1 < 3) ? __ldg(&b5[k1]) : 0.0f;
    }

    const long warpbase = (long)blockIdx.x * 1024 + w * 256;

    // ---- prefetch state ----
    float cu, cv, cz;     // coords for iteration it
    float nu, nv, nz;     // coords for iteration it+1
    uint4 cr0, cr1;       // gather results for iteration it
    unsigned cwxy;        // packed (wx, wy) for iteration it

    // coords loader (zero-fill out of range)
    auto load_coords = [&](int it, float& a, float& b, float& c) {
        long p = warpbase + (long)it * 32 + lane;
        if (it < 8 && p < (long)n) {
            a = __ldg(&x[p * 3 + 0]);
            b = __ldg(&x[p * 3 + 1]);
            c = __ldg(&x[p * 3 + 2]);
        } else {
            a = 0.0f; b = 0.0f; c = 0.0f;
        }
    };

    if (warpbase >= n) return;

    // prologue
    load_coords(0, cu, cv, cz);
    issue_gather(cu, cv, cr0, cr1, cwxy);
    load_coords(1, nu, nv, nz);

    for (int it = 0; it < 8; it++) {
        long pbase = warpbase + (long)it * 32;
        if (pbase >= n) break;                 // warp-uniform

        // ---- fp16 bilinear lerp on prefetched data ----
        __half2 wxyh = u2h(cwxy);
        __half2 wx2  = __low2half2(wxyh);
        __half2 wy2  = __high2half2(wxyh);

        __half2 A01 = u2h(cr0.x), A23 = u2h(cr0.y);
        __half2 B01 = u2h(cr0.z), B23 = u2h(cr0.w);
        __half2 Cc01 = u2h(cr1.x), Cc23 = u2h(cr1.y);
        __half2 D01 = u2h(cr1.z), D23 = u2h(cr1.w);

        __half2 t01 = __hfma2(wx2, __hsub2(B01, A01), A01);
        __half2 t23 = __hfma2(wx2, __hsub2(B23, A23), A23);
        __half2 s01 = __hfma2(wx2, __hsub2(D01, Cc01), Cc01);
        __half2 s23 = __hfma2(wx2, __hsub2(D23, Cc23), Cc23);
        __half2 f01 = __hfma2(wy2, __hsub2(s01, t01), t01);
        __half2 f23 = __hfma2(wy2, __hsub2(s23, t23), t23);

        // ---- stage input row: [x,y,z,0,f0,f1,f2,f3] ----
        uint4 row;
        row.x = h2u(cu, cv);
        row.y = h2u(cz, 0.0f);
        row.z = *reinterpret_cast<unsigned*>(&f01);
        row.w = *reinterpret_cast<unsigned*>(&f23);
        sIn[w][lane] = row;
        __syncwarp();

        // ---- ldmatrix x4: two m16k8 A fragments ----
        unsigned a0, a1, a2, a3;
        unsigned addr = (unsigned)__cvta_generic_to_shared(&sIn[w][lane]);
        asm volatile(
            "ldmatrix.sync.aligned.m8n8.x4.shared.b16 {%0,%1,%2,%3}, [%4];\n"
            : "=r"(a0), "=r"(a1), "=r"(a2), "=r"(a3)
            : "r"(addr));
        __syncwarp();   // sIn reusable next iteration

        // ---- prefetch: gathers for it+1, coords for it+2 ----
        issue_gather(nu, nv, cr0, cr1, cwxy);
        cu = nu; cv = nv; cz = nz;
        load_coords(it + 2, nu, nv, nz);

        // ---- layer 1 (k=8) ----
        unsigned A[2][4];
        {
            unsigned A1[2][2] = {{a0, a1}, {a2, a3}};
#pragma unroll
            for (int T = 0; T < 2; T++) {
                float c0[4] = {C1f[0][0], C1f[0][1], C1f[0][0], C1f[0][1]};
                float c1[4] = {C1f[1][0], C1f[1][1], C1f[1][0], C1f[1][1]};
                float d0[4], d1[4];
                mma_1688(d0, A1[T], B1f[0], c0);
                mma_1688(d1, A1[T], B1f[1], c1);
                A[T][0] = relu_pack(d0[0], d0[1]);
                A[T][1] = relu_pack(d0[2], d0[3]);
                A[T][2] = relu_pack(d1[0], d1[1]);
                A[T][3] = relu_pack(d1[2], d1[3]);
            }
        }

        // ---- layers 2-4 ----
        hidden16(A, B2f, C2f);
        hidden16(A, B3f, C3f);
        hidden16(A, B4f, C4f);

        // ---- layer 5 (n=3 padded to 8, single n-tile) ----
        float d5[2][4];
#pragma unroll
        for (int T = 0; T < 2; T++) {
            float c[4] = {C5f[0], C5f[1], C5f[0], C5f[1]};
            mma_16816(d5[T], A[T], B5f, c);
        }

        // ---- stage outputs ----
        if (q == 0) {
#pragma unroll
            for (int T = 0; T < 2; T++) {
                sOut[w][(T * 16 + g) * 3 + 0]     = d5[T][0];
                sOut[w][(T * 16 + g) * 3 + 1]     = d5[T][1];
                sOut[w][(T * 16 + g + 8) * 3 + 0] = d5[T][2];
                sOut[w][(T * 16 + g + 8) * 3 + 1] = d5[T][3];
            }
        } else if (q == 1) {
#pragma unroll
            for (int T = 0; T < 2; T++) {
                sOut[w][(T * 16 + g) * 3 + 2]     = d5[T][0];
                sOut[w][(T * 16 + g + 8) * 3 + 2] = d5[T][2];
            }
        }
        __syncwarp();

        // ---- store 96 contiguous floats ----
        if (pbase + 32 <= (long)n) {
            float4* dst = reinterpret_cast<float4*>(out + pbase * 3);
            const float4* src = reinterpret_cast<const float4*>(sOut[w]);
            if (lane < 24) dst[lane] = src[lane];
        } else {
            int cnt = (int)(n - pbase) * 3;
            for (int idx = lane; idx < cnt; idx += 32)
                out[pbase * 3 + idx] = sOut[w][idx];
        }
        __syncwarp();
    }
}

// ---------------------------------------------------------------------------
// kernel_launch — graph-capturable, allocation-free.
// ---------------------------------------------------------------------------
extern "C" void kernel_launch(void* const* d_in, const int* in_sizes, int n_in,
                              void* d_out, int out_size) {
    const float* x  = (const float*)d_in[0];
    const float* fm = (const float*)d_in[1];
    const float* W1 = (const float*)d_in[2];
    const float* b1 = (const float*)d_in[3];
    const float* W2 = (const float*)d_in[4];
    const float* b2 = (const float*)d_in[5];
    const float* W3 = (const float*)d_in[6];
    const float* b3 = (const float*)d_in[7];
    const float* W4 = (const float*)d_in[8];
    const float* b4 = (const float*)d_in[9];
    const float* W5 = (const float*)d_in[10];
    const float* b5 = (const float*)d_in[11];

    int n = in_sizes[0] / 3;   // 4,000,000 points

    fm_pack_kernel<<<(512 * 512 + 255) / 256, 256>>>(fm);

    int nblocks = (n + 1023) / 1024;   // 1024 points per block
    mlp_mma_kernel<<<nblocks, 128>>>(x, W1, b1, W2, b2, W3, b3, W4, b4, W5, b5,
                                     (float*)d_out, n);
}